// round 14
// baseline (speedup 1.0000x reference)
#include <cuda_runtime.h>
#include <cuda_bf16.h>

#define NATOMS 512
#define NBATCH 16
#define NP 16

typedef unsigned long long ull;

// ---- packed f32x2 helpers ----
__device__ __forceinline__ ull pk2(float lo, float hi) {
    ull r; asm("mov.b64 %0, {%1, %2};" : "=l"(r) : "f"(lo), "f"(hi)); return r;
}
__device__ __forceinline__ void upk2(float& lo, float& hi, ull v) {
    asm("mov.b64 {%0, %1}, %2;" : "=f"(lo), "=f"(hi) : "l"(v));
}
__device__ __forceinline__ ull mul2(ull a, ull b) {
    ull r; asm("mul.rn.f32x2 %0, %1, %2;" : "=l"(r) : "l"(a), "l"(b)); return r;
}
__device__ __forceinline__ ull add2(ull a, ull b) {
    ull r; asm("add.rn.f32x2 %0, %1, %2;" : "=l"(r) : "l"(a), "l"(b)); return r;
}
__device__ __forceinline__ ull fma2(ull a, ull b, ull c) {
    ull r; asm("fma.rn.f32x2 %0, %1, %2, %3;" : "=l"(r) : "l"(a), "l"(b), "l"(c)); return r;
}
__device__ __forceinline__ ull ex2_2(ull a) {   // packed exp2 via 2 scalar MUFU
    float lo, hi; upk2(lo, hi, a);
    asm("ex2.approx.ftz.f32 %0, %0;" : "+f"(lo));
    asm("ex2.approx.ftz.f32 %0, %0;" : "+f"(hi));
    return pk2(lo, hi);
}
__device__ __forceinline__ ull cos_2(ull a) {   // packed cos via 2 scalar MUFU
    float lo, hi; upk2(lo, hi, a);
    asm("cos.approx.ftz.f32 %0, %0;" : "+f"(lo));
    asm("cos.approx.ftz.f32 %0, %0;" : "+f"(hi));
    return pk2(lo, hi);
}

// ---- compile-time constants (constexpr repeated-multiply; no runtime pow) ----
constexpr double RQd = 0.09913776814937592;   // exp(-2*eta*dshf^2)
constexpr double rqp(int n) { double r = 1.0; for (int i = 0; i < n; ++i) r *= RQd; return r; }
constexpr double L2Ed = 1.4426950408889634;
constexpr double ETAd = 16.0, DSHd = 0.26875;

constexpr float C2f  = (float)(-ETAd * L2Ed);            // -eta*log2e
constexpr float A1f  = (float)( 2.0 * ETAd * DSHd * L2Ed);
constexpr float A0f  = (float)(-ETAd * DSHd * DSHd * L2Ed);
constexpr float RQ2f = (float)rqp(2);                    // T2k/T1k
constexpr float RQ4f = (float)rqp(4);                    // qk serial ratio
constexpr float T1_0f = (float)rqp(1),  T1_1f = (float)rqp(9),
                T1_2f = (float)rqp(17), T1_3f = (float)rqp(25);

// exp(-16*sp^2), sp = 0.9 + 0.26875*p : diagonal (d==0) correction
__constant__ float DIAG[16] = {
    2.3525e-6f, 3.1654e-10f, 4.3761e-15f, 5.8930e-21f,
    7.8650e-28f, 1.0413e-35f, 1.3600e-44f, 0.0f,
    0.0f, 0.0f, 0.0f, 0.0f, 0.0f, 0.0f, 0.0f, 0.0f};

__global__ void __launch_bounds__(128, 7) aev_radial_kernel(
    const float* __restrict__ dmat,   // [B, N, N]
    const float* __restrict__ zall,   // [B, N]
    float* __restrict__ out)          // [B, N, 16]
{
    constexpr float RCR       = 5.2f;
    constexpr float PI_OVER_R = 3.14159265358979323846f / 5.2f;
    constexpr float GSP       = 1.075f;                   // 4*dshf

    const int warp_g = (blockIdx.x * blockDim.x + threadIdx.x) >> 5;  // 0..4095
    const int lane   = threadIdx.x & 31;
    const int b      = warp_g >> 8;
    const int i0     = warp_g & 255;

    const float* __restrict__ zrow = zall + (size_t)b * NATOMS;
    const unsigned FULL = 0xffffffffu;

    // loop-invariant packed constants (uniform; expect UR promotion)
    const ull C2p   = pk2(C2f, C2f);
    const ull A1p   = pk2(A1f, A1f);
    const ull A0p   = pk2(A0f, A0f);
    const ull KCp   = pk2(PI_OVER_R, PI_OVER_R);
    const ull N09p  = pk2(-0.9f, -0.9f);
    const ull NGSPp = pk2(-GSP, -GSP);
    const ull RQ2p  = pk2(RQ2f, RQ2f);
    const ull RQ4p  = pk2(RQ4f, RQ4f);
    const ull T10p  = pk2(T1_0f, T1_0f);
    const ull T11p  = pk2(T1_1f, T1_1f);
    const ull T12p  = pk2(T1_2f, T1_2f);
    const ull T13p  = pk2(T1_3f, T1_3f);

#pragma unroll 1
    for (int half = 0; half < 2; ++half) {
        const int wg = b * NATOMS + i0 + half * 256;
        const float* __restrict__ row = dmat + (size_t)wg * NATOMS;

        // 16 packed accumulators: {sum over even pair-slots, sum over odd}
        ull acc[NP];
#pragma unroll
        for (int p = 0; p < NP; ++p) acc[p] = 0ull;

#pragma unroll
        for (int it = 0; it < 4; ++it) {
            const int j0 = it * 128 + lane * 4;
            const float4 dv = *reinterpret_cast<const float4*>(row  + j0);
            const float4 zv = *reinterpret_cast<const float4*>(zrow + j0);

#pragma unroll
            for (int pr = 0; pr < 2; ++pr) {     // two element-pairs per float4
                const float d0 = (pr == 0) ? dv.x : dv.z;
                const float d1 = (pr == 0) ? dv.y : dv.w;
                const float z0 = (pr == 0) ? zv.x : zv.z;
                const float z1 = (pr == 0) ? zv.y : zv.w;

                // clamp: fc(RCR) ~ 0 self-masks d>=RCR; diagonal fixed at store
                const ull dgp = pk2(fminf(d0, RCR), fminf(d1, RCR));
                const ull zp  = pk2(z0, z1);

                const ull cp = cos_2(mul2(dgp, KCp));
                const ull wp = fma2(zp, cp, zp);          // z*(cos+1); 0.5 at store

                ull up = add2(dgp, N09p);                 // u0 = dg - 0.9
                const ull qp0 = ex2_2(fma2(A1p, up, A0p));
                const ull sp  = mul2(qp0, qp0);           // bounded (dg<=RCR)
                ull qk = qp0;

                // k = 0
                {
                    const ull gp  = ex2_2(mul2(mul2(C2p, up), up));
                    const ull G   = mul2(wp, gp);
                    const ull GQ  = mul2(G, qk);
                    const ull ST1 = mul2(sp, T10p);
                    const ull ST2 = mul2(ST1, RQ2p);
                    acc[0] = add2(acc[0], G);
                    acc[1] = add2(acc[1], GQ);
                    acc[2] = fma2(G,  ST1, acc[2]);
                    acc[3] = fma2(GQ, ST2, acc[3]);
                }
                // k = 1
                {
                    up = add2(up, NGSPp);
                    qk = mul2(qk, RQ4p);
                    const ull gp  = ex2_2(mul2(mul2(C2p, up), up));
                    const ull G   = mul2(wp, gp);
                    const ull GQ  = mul2(G, qk);
                    const ull ST1 = mul2(sp, T11p);
                    const ull ST2 = mul2(ST1, RQ2p);
                    acc[4] = add2(acc[4], G);
                    acc[5] = add2(acc[5], GQ);
                    acc[6] = fma2(G,  ST1, acc[6]);
                    acc[7] = fma2(GQ, ST2, acc[7]);
                }
                // k = 2
                {
                    up = add2(up, NGSPp);
                    qk = mul2(qk, RQ4p);
                    const ull gp  = ex2_2(mul2(mul2(C2p, up), up));
                    const ull G   = mul2(wp, gp);
                    const ull GQ  = mul2(G, qk);
                    const ull ST1 = mul2(sp, T12p);
                    const ull ST2 = mul2(ST1, RQ2p);
                    acc[8]  = add2(acc[8],  G);
                    acc[9]  = add2(acc[9],  GQ);
                    acc[10] = fma2(G,  ST1, acc[10]);
                    acc[11] = fma2(GQ, ST2, acc[11]);
                }
                // k = 3
                {
                    up = add2(up, NGSPp);
                    qk = mul2(qk, RQ4p);
                    const ull gp  = ex2_2(mul2(mul2(C2p, up), up));
                    const ull G   = mul2(wp, gp);
                    const ull GQ  = mul2(G, qk);
                    const ull ST1 = mul2(sp, T13p);
                    const ull ST2 = mul2(ST1, RQ2p);
                    acc[12] = add2(acc[12], G);
                    acc[13] = add2(acc[13], GQ);
                    acc[14] = fma2(G,  ST1, acc[14]);
                    acc[15] = fma2(GQ, ST2, acc[15]);
                }
            }
        }

        // collapse packed halves, then halving reduction across lanes
        float a[NP];
#pragma unroll
        for (int p = 0; p < NP; ++p) {
            float lo, hi; upk2(lo, hi, acc[p]);
            a[p] = lo + hi;
        }

#pragma unroll
        for (int v = 0; v < 8; ++v) {
            const bool hi = (lane & 16);
            const float send = hi ? a[v] : a[v + 8];
            const float r = __shfl_xor_sync(FULL, send, 16);
            a[v] = (hi ? a[v + 8] : a[v]) + r;
        }
#pragma unroll
        for (int v = 0; v < 4; ++v) {
            const bool hi = (lane & 8);
            const float send = hi ? a[v] : a[v + 4];
            const float r = __shfl_xor_sync(FULL, send, 8);
            a[v] = (hi ? a[v + 4] : a[v]) + r;
        }
#pragma unroll
        for (int v = 0; v < 2; ++v) {
            const bool hi = (lane & 4);
            const float send = hi ? a[v] : a[v + 2];
            const float r = __shfl_xor_sync(FULL, send, 4);
            a[v] = (hi ? a[v + 2] : a[v]) + r;
        }
        {
            const bool hi = (lane & 2);
            const float send = hi ? a[0] : a[1];
            const float r = __shfl_xor_sync(FULL, send, 2);
            a[0] = (hi ? a[1] : a[0]) + r;
        }
        a[0] += __shfl_xor_sync(FULL, a[0], 1);

        if ((lane & 1) == 0) {
            const int f  = (lane >> 1) & 15;
            const float zi = zrow[i0 + half * 256];
            out[(size_t)wg * NP + f] = fmaf(0.5f, a[0], -zi * DIAG[f]);
        }
    }
}

extern "C" void kernel_launch(void* const* d_in, const int* in_sizes, int n_in,
                              void* d_out, int out_size)
{
    const float* dmat = (const float*)d_in[0];   // [16, 512, 512] float32
    const float* zall = (const float*)d_in[1];   // [16, 512] float32
    float* out        = (float*)d_out;           // [16, 512, 16] float32

    // 1024 blocks x 128 threads = 4096 warps; each warp does 2 rows.
    // Element-pair f32x2 packing halves the instruction stream;
    // launch_bounds(128,7) (<=73 regs) keeps the single balanced wave.
    aev_radial_kernel<<<1024, 128>>>(dmat, zall, out);
}